// round 1
// baseline (speedup 1.0000x reference)
#include <cuda_runtime.h>
#include <stdint.h>

// Problem constants (fixed shapes)
#define BTOT   65536
#define NF     256
#define NT     256
#define DEPTH  6
#define NC     4
#define NLEAF  (NT << DEPTH)     // 16384

#define THREADS        1024
#define ROWS_PER_ITER  8
#define NITERS         (BTOT / ROWS_PER_ITER)   // 8192

// SMEM layout (bytes):
//  root  256 int2  =  2048
//  l1    512 int2  =  4096
//  l2   1024 int2  =  8192
//  l3   2048 int2  = 16384
//  l4   4096 int2  = 32768
//  l5   8192 int2  = 65536   -> tables total 129024
//  x double buffer: 2 * 8*256*4 = 16384
//  argmax scratch : 8*4*256*4  = 32768
#define SMEM_BYTES (129024 + 16384 + 32768)

extern __shared__ unsigned char smem_raw[];

__global__ void __launch_bounds__(THREADS, 1)
tree_traverse_kernel(const float*  __restrict__ x,
                     const int*    __restrict__ root_nodes,
                     const float*  __restrict__ root_biases,
                     const float4* __restrict__ leaf,
                     const int* __restrict__ n1, const float* __restrict__ b1,
                     const int* __restrict__ n2, const float* __restrict__ b2,
                     const int* __restrict__ n3, const float* __restrict__ b3,
                     const int* __restrict__ n4, const float* __restrict__ b4,
                     const int* __restrict__ n5, const float* __restrict__ b5,
                     float*  __restrict__ out_amax,   // may be null
                     float4* __restrict__ out_vals,
                     int nblocks)
{
    int2* s_root = (int2*)smem_raw;        // 256
    int2* s1 = s_root + 256;               // 512
    int2* s2 = s1 + 512;                   // 1024
    int2* s3 = s2 + 1024;                  // 2048
    int2* s4 = s3 + 2048;                  // 4096
    int2* s5 = s4 + 4096;                  // 8192
    float* sx  = (float*)(s5 + 8192);      // 2 * 2048 floats
    float* sam = sx + 2 * 2048;            // 8192 floats

    const int tid  = threadIdx.x;
    const int t    = tid & 255;            // tree
    const int r0   = tid >> 8;             // 0..3 -> handles rows r0 and r0+4
    const int lane = tid & 31;
    const int wid  = tid >> 5;

    // ---- load packed split tables into shared ----
    {
        // 256 + 512 + 1024 + 2048 + 4096 + 8192 = 16128 entries
        for (int i = tid; i < 256;  i += THREADS) s_root[i] = make_int2(root_nodes[i], __float_as_int(root_biases[i]));
        for (int i = tid; i < 512;  i += THREADS) s1[i] = make_int2(n1[i], __float_as_int(b1[i]));
        for (int i = tid; i < 1024; i += THREADS) s2[i] = make_int2(n2[i], __float_as_int(b2[i]));
        for (int i = tid; i < 2048; i += THREADS) s3[i] = make_int2(n3[i], __float_as_int(b3[i]));
        for (int i = tid; i < 4096; i += THREADS) s4[i] = make_int2(n4[i], __float_as_int(b4[i]));
        for (int i = tid; i < 8192; i += THREADS) s5[i] = make_int2(n5[i], __float_as_int(b5[i]));
    }

    const int it0 = blockIdx.x;
    float pre0 = 0.f, pre1 = 0.f;
    if (it0 < NITERS) {
        size_t base = (size_t)it0 * ROWS_PER_ITER * NF;
        pre0 = x[base + tid];
        pre1 = x[base + 1024 + tid];
    }
    sx[tid]        = pre0;   // buffer 0
    sx[1024 + tid] = pre1;
    __syncthreads();

    int buf = 0;
    for (int it = it0; it < NITERS; it += nblocks) {
        const int nextit = it + nblocks;
        if (nextit < NITERS) {            // prefetch next x tile into registers
            size_t base = (size_t)nextit * ROWS_PER_ITER * NF;
            pre0 = x[base + tid];
            pre1 = x[base + 1024 + tid];
        }

        const size_t rowbase = (size_t)it * ROWS_PER_ITER;
        const float* xb = sx + buf * 2048;

        #pragma unroll
        for (int k = 0; k < 2; k++) {
            const int r = r0 + 4 * k;
            const float* xr = xb + r * NF;

            int2 e = s_root[t];
            int prev = 2 * t    + (xr[e.x] >= __int_as_float(e.y));
            e = s1[prev]; prev = 2 * prev + (xr[e.x] >= __int_as_float(e.y));
            e = s2[prev]; prev = 2 * prev + (xr[e.x] >= __int_as_float(e.y));
            e = s3[prev]; prev = 2 * prev + (xr[e.x] >= __int_as_float(e.y));
            e = s4[prev]; prev = 2 * prev + (xr[e.x] >= __int_as_float(e.y));
            e = s5[prev]; prev = 2 * prev + (xr[e.x] >= __int_as_float(e.y));

            const float4 lv = __ldg(leaf + prev);
            out_vals[(rowbase + r) * NT + t] = lv;

            float* sp = sam + (r * NC) * NT + t;     // [r][c][t] scratch
            sp[0 * NT] = lv.x;
            sp[1 * NT] = lv.y;
            sp[2 * NT] = lv.z;
            sp[3 * NT] = lv.w;
        }
        __syncthreads();

        if (out_amax) {
            // warp `wid` reduces (row = wid>>2, class = wid&3) over 256 trees,
            // first-index tie-break to match jnp.argmax.
            const float* sp = sam + wid * NT;
            float best = sp[lane];
            int   bidx = lane;
            #pragma unroll
            for (int e2 = lane + 32; e2 < NT; e2 += 32) {
                float v = sp[e2];
                if (v > best) { best = v; bidx = e2; }   // ascending -> keeps lowest idx on tie
            }
            #pragma unroll
            for (int off = 16; off; off >>= 1) {
                float ov = __shfl_down_sync(0xffffffffu, best, off);
                int   oi = __shfl_down_sync(0xffffffffu, bidx, off);
                if (ov > best || (ov == best && oi < bidx)) { best = ov; bidx = oi; }
            }
            if (lane == 0) {
                const int rr = wid >> 2, cc = wid & 3;
                out_amax[(rowbase + rr) * NC + cc] = (float)bidx;
            }
        }

        buf ^= 1;
        sx[buf * 2048 + tid]        = pre0;
        sx[buf * 2048 + 1024 + tid] = pre1;
        __syncthreads();
    }
}

extern "C" void kernel_launch(void* const* d_in, const int* in_sizes, int n_in,
                              void* d_out, int out_size)
{
    const float*  x     = (const float*) d_in[0];
    const int*    rn    = (const int*)   d_in[1];
    const float*  rb    = (const float*) d_in[2];
    const float4* leaf  = (const float4*)d_in[3];
    const int*    n1 = (const int*)d_in[4];   const float* b1 = (const float*)d_in[5];
    const int*    n2 = (const int*)d_in[6];   const float* b2 = (const float*)d_in[7];
    const int*    n3 = (const int*)d_in[8];   const float* b3 = (const float*)d_in[9];
    const int*    n4 = (const int*)d_in[10];  const float* b4 = (const float*)d_in[11];
    const int*    n5 = (const int*)d_in[12];  const float* b5 = (const float*)d_in[13];

    const int vals_n = BTOT * NT * NC;   // 67108864
    const int amax_n = BTOT * NC;        // 262144

    float*  out_amax = 0;
    float4* out_vals;
    if (out_size == vals_n + amax_n) {
        out_amax = (float*)d_out;                       // tuple order: (argmax, out)
        out_vals = (float4*)((float*)d_out + amax_n);
    } else {
        out_vals = (float4*)d_out;                      // values only
    }

    int dev = 0, sms = 148;
    cudaGetDevice(&dev);
    cudaDeviceGetAttribute(&sms, cudaDevAttrMultiProcessorCount, dev);
    if (sms <= 0) sms = 148;

    cudaFuncSetAttribute(tree_traverse_kernel,
                         cudaFuncAttributeMaxDynamicSharedMemorySize, SMEM_BYTES);

    tree_traverse_kernel<<<sms, THREADS, SMEM_BYTES>>>(
        x, rn, rb, leaf,
        n1, b1, n2, b2, n3, b3, n4, b4, n5, b5,
        out_amax, out_vals, sms);
}

// round 2
// speedup vs baseline: 1.2937x; 1.2937x over previous
#include <cuda_runtime.h>
#include <stdint.h>

#define BTOT   65536
#define NF     256
#define NT     256
#define NC     4
#define TILE_R 32
#define NITERS (BTOT / TILE_R)   // 2048
#define THREADS 1024

// shared-memory byte offsets
#define OFF_ROOT 0            // int2[256]    2048 B
#define OFF_L1   2048         // int2[512]    4096 B
#define OFF_L2   6144         // int2[1024]   8192 B
#define OFF_L3   14336        // int2[2048]  16384 B
#define OFF_L4   30720        // int2[4096]  32768 B
#define OFF_XT   63488        // float[2][8192] (transposed x tiles [f][r]) 65536 B
#define OFF_XTMP 129024       // float[8192]    (row-major staging)        32768 B
#define OFF_SCR  161792       // float4[2][1056] (leaf transpose, pad 33)  33792 B
#define OFF_AMX  195584       // u64[4254]      (argmax partials)          34032 B
#define SMEM_BYTES 229616

extern __shared__ unsigned char smem_raw[];

// monotone float -> orderable uint map (no NaNs in data)
__device__ __forceinline__ unsigned fmap(float f) {
    unsigned u = __float_as_uint(f);
    return (u & 0x80000000u) ? ~u : (u | 0x80000000u);
}

__global__ void __launch_bounds__(THREADS, 1)
tree_kernel(const float*  __restrict__ x,
            const int*    __restrict__ rn, const float* __restrict__ rb,
            const float4* __restrict__ leaf,
            const int* __restrict__ n1, const float* __restrict__ b1,
            const int* __restrict__ n2, const float* __restrict__ b2,
            const int* __restrict__ n3, const float* __restrict__ b3,
            const int* __restrict__ n4, const float* __restrict__ b4,
            const int* __restrict__ n5, const float* __restrict__ b5,
            float*  __restrict__ out_amax,     // may be null
            float4* __restrict__ out_vals,
            int nb)
{
    int2*   s_root = (int2*)  (smem_raw + OFF_ROOT);
    int2*   s1     = (int2*)  (smem_raw + OFF_L1);
    int2*   s2     = (int2*)  (smem_raw + OFF_L2);
    int2*   s3     = (int2*)  (smem_raw + OFF_L3);
    int2*   s4     = (int2*)  (smem_raw + OFF_L4);
    float*  sxT    = (float*) (smem_raw + OFF_XT);
    float*  sxtmp  = (float*) (smem_raw + OFF_XTMP);
    float4* sscr   = (float4*)(smem_raw + OFF_SCR);
    unsigned long long* samx = (unsigned long long*)(smem_raw + OFF_AMX);

    const int tid  = threadIdx.x;
    const int w    = tid >> 5;     // warp id = tree slot
    const int lane = tid & 31;     // lane    = row within tile

    // ---- split tables root..l4 into shared (l5 stays in gmem: per-tree slice = one 128B line) ----
    for (int i = tid; i < 256;  i += THREADS) s_root[i] = make_int2(rn[i], __float_as_int(rb[i]));
    for (int i = tid; i < 512;  i += THREADS) s1[i] = make_int2(n1[i], __float_as_int(b1[i]));
    for (int i = tid; i < 1024; i += THREADS) s2[i] = make_int2(n2[i], __float_as_int(b2[i]));
    for (int i = tid; i < 2048; i += THREADS) s3[i] = make_int2(n3[i], __float_as_int(b3[i]));
    for (int i = tid; i < 4096; i += THREADS) s4[i] = make_int2(n4[i], __float_as_int(b4[i]));

    // ---- prologue: stage + transpose first x tile into sxT[0] ----
    int it = blockIdx.x;
    if (it < NITERS) {
        size_t base = (size_t)it * (TILE_R * NF);
        #pragma unroll
        for (int j = 0; j < 8; j++) sxtmp[tid + j * 1024] = x[base + tid + j * 1024];
    }
    __syncthreads();
    if (it < NITERS) {
        #pragma unroll
        for (int j = 0; j < 8; j++) {              // diagonal transpose, conflict-free both sides
            int f = (j << 5) | lane;
            int r = (lane + w) & 31;
            sxT[f * 32 + r] = sxtmp[r * 256 + f];
        }
    }
    __syncthreads();

    int xbuf = 0;
    int prevrb = -1;

    for (; it < NITERS; it += nb) {
        const int rowbase = it * TILE_R;
        const int nextit  = it + nb;

        // ---- finish argmax for the previous tile (reads samx, synced long ago) ----
        if (prevrb >= 0 && out_amax) {
            #pragma unroll
            for (int c = 0; c < 4; c++) {
                unsigned long long bk = samx[lane * 133 + c * 33 + w];  // partial of gather-warp `lane`, row `w`
                #pragma unroll
                for (int off = 16; off; off >>= 1) {
                    unsigned long long o = __shfl_down_sync(0xFFFFFFFFu, bk, off);
                    if (o > bk) bk = o;
                }
                if (lane == 0) {
                    int t = 255 - (int)(bk & 0xFFFFFFFFull);
                    out_amax[(size_t)(prevrb + w) * NC + c] = (float)t;
                }
            }
        }

        unsigned long long best0 = 0, best1 = 0, best2 = 0, best3 = 0;
        const float* xc = sxT + xbuf * 8192;   // [f][r], read addr f*32+lane -> bank==lane

        #pragma unroll
        for (int k = 0; k < 8; k++) {
            const int t = (k << 5) + w;        // this warp's tree for this step

            int2 e = s_root[t];
            unsigned p = (unsigned)(t << 1) + (xc[(e.x << 5) + lane] >= __int_as_float(e.y));
            e = s1[p]; p = (p << 1) + (xc[(e.x << 5) + lane] >= __int_as_float(e.y));
            e = s2[p]; p = (p << 1) + (xc[(e.x << 5) + lane] >= __int_as_float(e.y));
            e = s3[p]; p = (p << 1) + (xc[(e.x << 5) + lane] >= __int_as_float(e.y));
            e = s4[p]; p = (p << 1) + (xc[(e.x << 5) + lane] >= __int_as_float(e.y));
            // level 5 via gmem: all 32 lanes inside one aligned 128B line of n5/b5
            int   f5 = __ldg(n5 + p);
            float g5 = __ldg(b5 + p);
            p = (p << 1) + (xc[(f5 << 5) + lane] >= g5);

            const float4 lv = __ldg(leaf + p); // 32 lanes within one 1KB region: <=8 lines

            // running argmax (key: high=ordered value bits, low=255-t -> max == first-index argmax)
            unsigned long long kx;
            kx = ((unsigned long long)fmap(lv.x) << 32) | (unsigned)(255 - t); if (kx > best0) best0 = kx;
            kx = ((unsigned long long)fmap(lv.y) << 32) | (unsigned)(255 - t); if (kx > best1) best1 = kx;
            kx = ((unsigned long long)fmap(lv.z) << 32) | (unsigned)(255 - t); if (kx > best2) best2 = kx;
            kx = ((unsigned long long)fmap(lv.w) << 32) | (unsigned)(255 - t); if (kx > best3) best3 = kx;

            // stage for coalesced writeback: [gather-warp][row], pad 33
            sscr[(k & 1) * 1056 + w * 33 + lane] = lv;
            __syncthreads();
            // writeback: warp w = row w, lanes = 32 consecutive trees -> 1 line per row
            float4 v = sscr[(k & 1) * 1056 + lane * 33 + w];
            out_vals[(size_t)(rowbase + w) * NT + (k << 5) + lane] = v;
        }

        // ---- post-gather segment: argmax partials + stage next x tile ----
        if (out_amax) {
            samx[w * 133 + 0 * 33 + lane] = best0;
            samx[w * 133 + 1 * 33 + lane] = best1;
            samx[w * 133 + 2 * 33 + lane] = best2;
            samx[w * 133 + 3 * 33 + lane] = best3;
        }
        if (nextit < NITERS) {
            size_t base = (size_t)nextit * (TILE_R * NF);
            #pragma unroll
            for (int j = 0; j < 8; j++) sxtmp[tid + j * 1024] = x[base + tid + j * 1024];
        }
        __syncthreads();
        if (nextit < NITERS) {
            float* xn = sxT + (xbuf ^ 1) * 8192;
            #pragma unroll
            for (int j = 0; j < 8; j++) {
                int f = (j << 5) | lane;
                int r = (lane + w) & 31;
                xn[f * 32 + r] = sxtmp[r * 256 + f];
            }
        }
        __syncthreads();
        xbuf ^= 1;
        prevrb = rowbase;
    }

    // ---- epilogue: argmax for the last tile this block processed ----
    if (prevrb >= 0 && out_amax) {
        #pragma unroll
        for (int c = 0; c < 4; c++) {
            unsigned long long bk = samx[lane * 133 + c * 33 + w];
            #pragma unroll
            for (int off = 16; off; off >>= 1) {
                unsigned long long o = __shfl_down_sync(0xFFFFFFFFu, bk, off);
                if (o > bk) bk = o;
            }
            if (lane == 0) {
                int t = 255 - (int)(bk & 0xFFFFFFFFull);
                out_amax[(size_t)(prevrb + w) * NC + c] = (float)t;
            }
        }
    }
}

extern "C" void kernel_launch(void* const* d_in, const int* in_sizes, int n_in,
                              void* d_out, int out_size)
{
    const float*  x    = (const float*) d_in[0];
    const int*    rn   = (const int*)   d_in[1];
    const float*  rb   = (const float*) d_in[2];
    const float4* leaf = (const float4*)d_in[3];
    const int*   n1 = (const int*)d_in[4];   const float* b1 = (const float*)d_in[5];
    const int*   n2 = (const int*)d_in[6];   const float* b2 = (const float*)d_in[7];
    const int*   n3 = (const int*)d_in[8];   const float* b3 = (const float*)d_in[9];
    const int*   n4 = (const int*)d_in[10];  const float* b4 = (const float*)d_in[11];
    const int*   n5 = (const int*)d_in[12];  const float* b5 = (const float*)d_in[13];

    const int vals_n = BTOT * NT * NC;   // 67108864
    const int amax_n = BTOT * NC;        // 262144

    float*  out_amax = 0;
    float4* out_vals;
    if (out_size == vals_n + amax_n) {
        out_amax = (float*)d_out;                    // tuple order: (argmax, out)
        out_vals = (float4*)((float*)d_out + amax_n);
    } else {
        out_vals = (float4*)d_out;                   // values only
    }

    int dev = 0, sms = 148;
    cudaGetDevice(&dev);
    cudaDeviceGetAttribute(&sms, cudaDevAttrMultiProcessorCount, dev);
    if (sms <= 0) sms = 148;

    cudaFuncSetAttribute(tree_kernel,
                         cudaFuncAttributeMaxDynamicSharedMemorySize, SMEM_BYTES);

    tree_kernel<<<sms, THREADS, SMEM_BYTES>>>(
        x, rn, rb, leaf,
        n1, b1, n2, b2, n3, b3, n4, b4, n5, b5,
        out_amax, out_vals, sms);
}

// round 3
// speedup vs baseline: 1.5306x; 1.1831x over previous
#include <cuda_runtime.h>
#include <stdint.h>

#define BTOT   65536
#define NF     256
#define NT     256
#define NC     4
#define TILE_R 32
#define NITERS (BTOT / TILE_R)   // 2048
#define THREADS 1024

// shared-memory byte offsets
#define OFF_ROOT 0            // int2[256]    2048 B
#define OFF_L1   2048         // int2[512]    4096 B
#define OFF_L2   6144         // int2[1024]   8192 B
#define OFF_L3   14336        // int2[2048]  16384 B
#define OFF_L4   30720        // int2[4096]  32768 B
#define OFF_XT   63488        // float[2][8192] transposed x tiles [f][32]  65536 B
#define OFF_XTMP 129024       // float[8192]    row-major staging          32768 B
#define OFF_SCR  161792       // float4[2][1056] leaf transpose (pad 33)   33792 B
#define OFF_AMX  195584       // u64[32*133]    argmax partials            34048 B
#define SMEM_BYTES 229632

__device__ int2 g_l5[8192];   // packed level-5 {feat, bias-bits}

extern __shared__ unsigned char smem_raw[];

__device__ __forceinline__ unsigned fmap(float f) {
    unsigned u = __float_as_uint(f);
    return (u & 0x80000000u) ? ~u : (u | 0x80000000u);
}

__device__ __forceinline__ void cp_async16(void* smem_dst, const void* gmem_src) {
    unsigned saddr = (unsigned)__cvta_generic_to_shared(smem_dst);
    asm volatile("cp.async.cg.shared.global [%0], [%1], 16;" :: "r"(saddr), "l"(gmem_src));
}

__global__ void pack_l5_kernel(const int* __restrict__ n5, const float* __restrict__ b5) {
    int i = blockIdx.x * blockDim.x + threadIdx.x;
    if (i < 8192) g_l5[i] = make_int2(n5[i], __float_as_int(b5[i]));
}

__global__ void __launch_bounds__(THREADS, 1)
tree_kernel(const float*  __restrict__ x,
            const int*    __restrict__ rn, const float* __restrict__ rb,
            const float4* __restrict__ leaf,
            const int* __restrict__ n1, const float* __restrict__ b1,
            const int* __restrict__ n2, const float* __restrict__ b2,
            const int* __restrict__ n3, const float* __restrict__ b3,
            const int* __restrict__ n4, const float* __restrict__ b4,
            float*  __restrict__ out_amax,     // may be null
            float4* __restrict__ out_vals,
            int nb)
{
    int2*   s_root = (int2*)  (smem_raw + OFF_ROOT);
    int2*   s1     = (int2*)  (smem_raw + OFF_L1);
    int2*   s2     = (int2*)  (smem_raw + OFF_L2);
    int2*   s3     = (int2*)  (smem_raw + OFF_L3);
    int2*   s4     = (int2*)  (smem_raw + OFF_L4);
    float*  sxT    = (float*) (smem_raw + OFF_XT);
    float*  sxtmp  = (float*) (smem_raw + OFF_XTMP);
    float4* sscr   = (float4*)(smem_raw + OFF_SCR);
    unsigned long long* samx = (unsigned long long*)(smem_raw + OFF_AMX);

    const int tid  = threadIdx.x;
    const int w    = tid >> 5;
    const int lane = tid & 31;

    for (int i = tid; i < 256;  i += THREADS) s_root[i] = make_int2(rn[i], __float_as_int(rb[i]));
    for (int i = tid; i < 512;  i += THREADS) s1[i] = make_int2(n1[i], __float_as_int(b1[i]));
    for (int i = tid; i < 1024; i += THREADS) s2[i] = make_int2(n2[i], __float_as_int(b2[i]));
    for (int i = tid; i < 2048; i += THREADS) s3[i] = make_int2(n3[i], __float_as_int(b3[i]));
    for (int i = tid; i < 4096; i += THREADS) s4[i] = make_int2(n4[i], __float_as_int(b4[i]));

    // ---- prologue: stage + transpose first x tile ----
    int it = blockIdx.x;
    if (it < NITERS) {
        const float4* xb4 = (const float4*)(x + (size_t)it * (TILE_R * NF));
        ((float4*)sxtmp)[tid]        = xb4[tid];
        ((float4*)sxtmp)[tid + 1024] = xb4[tid + 1024];
    }
    __syncthreads();
    if (it < NITERS) {
        #pragma unroll
        for (int j = 0; j < 8; j++) {
            int f = (j << 5) | lane;
            int r = (lane + w) & 31;
            sxT[f * 32 + r] = sxtmp[r * 256 + f];
        }
    }
    __syncthreads();

    int xbuf = 0;
    int prevrb = -1;

    for (; it < NITERS; it += nb) {
        const int rowbase = it * TILE_R;
        const int nextit  = it + nb;

        // prefetch next tile's x into sxtmp (overlaps whole gather phase)
        if (nextit < NITERS) {
            const float4* xb4 = (const float4*)(x + (size_t)nextit * (TILE_R * NF));
            cp_async16(((float4*)sxtmp) + tid,        xb4 + tid);
            cp_async16(((float4*)sxtmp) + tid + 1024, xb4 + tid + 1024);
        }
        asm volatile("cp.async.commit_group;");

        // finish previous tile's argmax (samx synced at end of prev tile)
        if (prevrb >= 0 && out_amax) {
            #pragma unroll
            for (int c = 0; c < 4; c++) {
                unsigned long long bk = samx[lane * 133 + c * 33 + w];
                #pragma unroll
                for (int off = 16; off; off >>= 1) {
                    unsigned long long o = __shfl_down_sync(0xFFFFFFFFu, bk, off);
                    if (o > bk) bk = o;
                }
                if (lane == 0)
                    out_amax[(size_t)(prevrb + w) * NC + c] =
                        (float)(255 - (int)(bk & 0xFFFFFFFFull));
            }
        }

        unsigned bv0 = 0, bv1 = 0, bv2 = 0, bv3 = 0;
        unsigned bi0 = 0, bi1 = 0, bi2 = 0, bi3 = 0;
        const float* xc = sxT + xbuf * 8192;

        #pragma unroll
        for (int j = 0; j < 4; j++) {
            if (j > 0) __syncthreads();              // sscr free from previous pair
            const int ta = (j << 6) + w;
            const int tb = ta + 32;

            // two interleaved independent chains
            int2 ea = s_root[ta];
            int2 eb = s_root[tb];
            unsigned pa = (unsigned)(ta << 1) + (xc[(ea.x << 5) + lane] >= __int_as_float(ea.y));
            unsigned pb = (unsigned)(tb << 1) + (xc[(eb.x << 5) + lane] >= __int_as_float(eb.y));
            ea = s1[pa]; eb = s1[pb];
            pa = (pa << 1) + (xc[(ea.x << 5) + lane] >= __int_as_float(ea.y));
            pb = (pb << 1) + (xc[(eb.x << 5) + lane] >= __int_as_float(eb.y));
            ea = s2[pa]; eb = s2[pb];
            pa = (pa << 1) + (xc[(ea.x << 5) + lane] >= __int_as_float(ea.y));
            pb = (pb << 1) + (xc[(eb.x << 5) + lane] >= __int_as_float(eb.y));
            ea = s3[pa]; eb = s3[pb];
            pa = (pa << 1) + (xc[(ea.x << 5) + lane] >= __int_as_float(ea.y));
            pb = (pb << 1) + (xc[(eb.x << 5) + lane] >= __int_as_float(eb.y));
            ea = s4[pa]; eb = s4[pb];
            pa = (pa << 1) + (xc[(ea.x << 5) + lane] >= __int_as_float(ea.y));
            pb = (pb << 1) + (xc[(eb.x << 5) + lane] >= __int_as_float(eb.y));
            ea = __ldg(g_l5 + pa); eb = __ldg(g_l5 + pb);
            pa = (pa << 1) + (xc[(ea.x << 5) + lane] >= __int_as_float(ea.y));
            pb = (pb << 1) + (xc[(eb.x << 5) + lane] >= __int_as_float(eb.y));

            const float4 lva = __ldg(leaf + pa);
            const float4 lvb = __ldg(leaf + pb);

            unsigned v;
            v = fmap(lva.x); if (v > bv0) { bv0 = v; bi0 = ta; }
            v = fmap(lva.y); if (v > bv1) { bv1 = v; bi1 = ta; }
            v = fmap(lva.z); if (v > bv2) { bv2 = v; bi2 = ta; }
            v = fmap(lva.w); if (v > bv3) { bv3 = v; bi3 = ta; }
            v = fmap(lvb.x); if (v > bv0) { bv0 = v; bi0 = tb; }
            v = fmap(lvb.y); if (v > bv1) { bv1 = v; bi1 = tb; }
            v = fmap(lvb.z); if (v > bv2) { bv2 = v; bi2 = tb; }
            v = fmap(lvb.w); if (v > bv3) { bv3 = v; bi3 = tb; }

            sscr[w * 33 + lane]        = lva;
            sscr[1056 + w * 33 + lane] = lvb;
            __syncthreads();
            float4 va = sscr[lane * 33 + w];
            float4 vb = sscr[1056 + lane * 33 + w];
            float4* op = out_vals + (size_t)(rowbase + w) * NT + (j << 6) + lane;
            op[0]  = va;
            op[32] = vb;
        }

        // argmax partials: pack (ordered-val | 255 - tree) for first-index tie-break
        if (out_amax) {
            samx[w * 133 + 0 * 33 + lane] = ((unsigned long long)bv0 << 32) | (unsigned)(255 - bi0);
            samx[w * 133 + 1 * 33 + lane] = ((unsigned long long)bv1 << 32) | (unsigned)(255 - bi1);
            samx[w * 133 + 2 * 33 + lane] = ((unsigned long long)bv2 << 32) | (unsigned)(255 - bi2);
            samx[w * 133 + 3 * 33 + lane] = ((unsigned long long)bv3 << 32) | (unsigned)(255 - bi3);
        }

        asm volatile("cp.async.wait_group 0;");
        __syncthreads();                      // sscr reads done + sxtmp fully landed
        if (nextit < NITERS) {
            float* xn = sxT + (xbuf ^ 1) * 8192;
            #pragma unroll
            for (int j = 0; j < 8; j++) {
                int f = (j << 5) | lane;
                int r = (lane + w) & 31;
                xn[f * 32 + r] = sxtmp[r * 256 + f];
            }
        }
        __syncthreads();
        xbuf ^= 1;
        prevrb = rowbase;
    }

    // epilogue: argmax for last tile processed by this block
    if (prevrb >= 0 && out_amax) {
        #pragma unroll
        for (int c = 0; c < 4; c++) {
            unsigned long long bk = samx[lane * 133 + c * 33 + w];
            #pragma unroll
            for (int off = 16; off; off >>= 1) {
                unsigned long long o = __shfl_down_sync(0xFFFFFFFFu, bk, off);
                if (o > bk) bk = o;
            }
            if (lane == 0)
                out_amax[(size_t)(prevrb + w) * NC + c] =
                    (float)(255 - (int)(bk & 0xFFFFFFFFull));
        }
    }
}

extern "C" void kernel_launch(void* const* d_in, const int* in_sizes, int n_in,
                              void* d_out, int out_size)
{
    const float*  x    = (const float*) d_in[0];
    const int*    rn   = (const int*)   d_in[1];
    const float*  rb   = (const float*) d_in[2];
    const float4* leaf = (const float4*)d_in[3];
    const int*   n1 = (const int*)d_in[4];   const float* b1 = (const float*)d_in[5];
    const int*   n2 = (const int*)d_in[6];   const float* b2 = (const float*)d_in[7];
    const int*   n3 = (const int*)d_in[8];   const float* b3 = (const float*)d_in[9];
    const int*   n4 = (const int*)d_in[10];  const float* b4 = (const float*)d_in[11];
    const int*   n5 = (const int*)d_in[12];  const float* b5 = (const float*)d_in[13];

    const int vals_n = BTOT * NT * NC;
    const int amax_n = BTOT * NC;

    float*  out_amax = 0;
    float4* out_vals;
    if (out_size == vals_n + amax_n) {
        out_amax = (float*)d_out;
        out_vals = (float4*)((float*)d_out + amax_n);
    } else {
        out_vals = (float4*)d_out;
    }

    int dev = 0, sms = 148;
    cudaGetDevice(&dev);
    cudaDeviceGetAttribute(&sms, cudaDevAttrMultiProcessorCount, dev);
    if (sms <= 0) sms = 148;

    pack_l5_kernel<<<8, 1024>>>(n5, b5);

    cudaFuncSetAttribute(tree_kernel,
                         cudaFuncAttributeMaxDynamicSharedMemorySize, SMEM_BYTES);

    tree_kernel<<<sms, THREADS, SMEM_BYTES>>>(
        x, rn, rb, leaf,
        n1, b1, n2, b2, n3, b3, n4, b4,
        out_amax, out_vals, sms);
}